// round 12
// baseline (speedup 1.0000x reference)
#include <cuda_runtime.h>
#include <cuda_fp16.h>
#include <cstdint>

// Transposed conv (full conv): B=8, H=W=256, CIN=COUT=64, 3x3, fp32 NHWC.
// out[b,p,q,co] = sum_{di,dj,ci} in[b,p-di,q-dj,ci] * ker[ci,co,di,dj]
// Kernel 1: preconvert fp32->fp16 (pre-swizzled) + tail columns (q=256,257).
// Kernel 2: mma.sync fp16 implicit GEMM; rows via cp.async; A-fragment
// rolling window shares input rows across the warp's two output rows.

#define IH 256
#define IW 256
#define NCH 64
#define OH 258
#define OW 258

// main-kernel smem layout
#define B_TAP 8192                        // per tap: 64 co rows x 128B fp16
#define SM_B 0
#define SM_A (9 * B_TAP)                  // 73728
#define A_SLOT 8704                       // 68 px segs * 128B
#define NSLOT 16
#define SM_TOTAL (SM_A + NSLOT * A_SLOT)  // 212992

#define NPB 43                            // 6-row units per strip (43*6=258)
#define NSTRIP 32                         // 8 b * 4 q-strips of 64
#define NMAIN (NSTRIP * NPB)              // 1376
#define NTPX (8 * OH * 2)                 // 4128 tail pixels
#define NTAIL 65
#define NCTA 152
#define NTHR 768

#define PREBLKS (IH * 8)                  // 2048 preconvert blocks
#define SM_PT (SM_A + 8192)               // prepass/tail smem: W taps + A tile

#define GROW 32768                        // bytes per pre-converted input row

// 64MB pre-converted fp16 input: [b][r][pa][ci], 128B per px, SW128 by abs px
__device__ __align__(128) unsigned char g_fp16[(size_t)8 * IH * GROW];

__device__ __forceinline__ uint32_t smem_u32(const void* p) {
    uint32_t a;
    asm("{ .reg .u64 t; cvta.to.shared.u64 t, %1; cvt.u32.u64 %0, t; }" : "=r"(a) : "l"(p));
    return a;
}
__device__ __forceinline__ void ldm4(uint32_t* r, uint32_t a) {
    asm volatile("ldmatrix.sync.aligned.m8n8.x4.shared.b16 {%0,%1,%2,%3}, [%4];"
                 : "=r"(r[0]), "=r"(r[1]), "=r"(r[2]), "=r"(r[3]) : "r"(a));
}
__device__ __forceinline__ void mma16816(float* c, const uint32_t* a,
                                         uint32_t b0, uint32_t b1) {
    asm volatile(
        "mma.sync.aligned.m16n8k16.row.col.f32.f16.f16.f32 "
        "{%0,%1,%2,%3}, {%4,%5,%6,%7}, {%8,%9}, {%0,%1,%2,%3};"
        : "+f"(c[0]), "+f"(c[1]), "+f"(c[2]), "+f"(c[3])
        : "r"(a[0]), "r"(a[1]), "r"(a[2]), "r"(a[3]), "r"(b0), "r"(b1));
}
__device__ __forceinline__ void cp16(uint32_t dst, const void* src) {
    asm volatile(
        "{ .reg .u64 g; cvta.to.global.u64 g, %1; cp.async.cg.shared.global [%0], [g], 16; }"
        :: "r"(dst), "l"(src) : "memory");
}
__device__ __forceinline__ void cpcommit() {
    asm volatile("cp.async.commit_group;" ::: "memory");
}
template <int N>
__device__ __forceinline__ void cpwait() {
    asm volatile("cp.async.wait_group %0;" :: "n"(N) : "memory");
}

// ---- kernel 1: preconvert (blocks 0..2047) + tail units (blocks 2048..2112) ----
__global__ void __launch_bounds__(256)
pre_and_tail_kernel(const float* __restrict__ gin, const float* __restrict__ gw,
                    float* __restrict__ gout)
{
    if (blockIdx.x < PREBLKS) {
        const int r = blockIdx.x & 255;
        const int b = blockIdx.x >> 8;
        const float* src = gin + ((size_t)b * IH + r) * IW * NCH;
        unsigned char* dst = g_fp16 + ((size_t)b * IH + r) * GROW;
#pragma unroll 4
        for (int idx = threadIdx.x; idx < IW * 16; idx += 256) {
            int pa = idx >> 4, c4 = idx & 15;
            float4 v = __ldg((const float4*)(src + (size_t)pa * NCH + c4 * 4));
            __half2 h01 = make_half2(__float2half_rn(v.x), __float2half_rn(v.y));
            __half2 h23 = make_half2(__float2half_rn(v.z), __float2half_rn(v.w));
            uint32_t off = (uint32_t)pa * 128 + (uint32_t)c4 * 8;
            uint32_t sw = off ^ ((off >> 3) & 0x70);
            *(uint2*)(dst + sw) = make_uint2(*(uint32_t*)&h01, *(uint32_t*)&h23);
        }
        return;
    }

    // ---- tail unit: 64 packed pixels from q in {256,257} ----
    extern __shared__ char smem[];
    const uint32_t sb = smem_u32(smem);
    const int tid = threadIdx.x;
    const int lane = tid & 31;
    const int wid = tid >> 5;
    const int g0 = (blockIdx.x - PREBLKS) * 64;

    // weights: all 9 taps, W^T[co][ci] fp16 SW128
    for (int e = tid; e < NCH * NCH; e += 256) {
        int ci = e >> 6, co = e & 63;
        const float* wp = gw + (size_t)e * 9;
        uint32_t off = (uint32_t)co * 128 + (uint32_t)ci * 2;
        uint32_t sw = off ^ ((off >> 3) & 0x70);
#pragma unroll
        for (int tap = 0; tap < 9; tap++) {
            __half h = __float2half_rn(wp[tap]);
            *(unsigned short*)(smem + SM_B + tap * B_TAP + sw) = __half_as_ushort(h);
        }
    }

    const int lm = (lane & 7) + ((lane >> 3) & 1) * 8;
    const uint32_t kcl = (uint32_t)((lane >> 4) & 1) * 16;
    const int tm = wid & 3;
    const int tn = wid >> 2;          // 0..1
    const int tnl0 = tn * 32 + lm;
    const int tnl1 = tnl0 + 16;
    const uint32_t tbrow0 = (uint32_t)tnl0 * 128, tbm0 = (uint32_t)(tnl0 & 7) << 4;
    const uint32_t tbrow1 = (uint32_t)tnl1 * 128, tbm1 = (uint32_t)(tnl1 & 7) << 4;
    const int rowi = tm * 16 + lm;
    const uint32_t arow = (uint32_t)rowi * 128;
    const uint32_t am = (uint32_t)(rowi & 7) << 4;

    float ct[4][4];
#pragma unroll
    for (int i = 0; i < 4; i++)
#pragma unroll
        for (int j = 0; j < 4; j++) ct[i][j] = 0.f;

    for (int tap = 0; tap < 9; tap++) {
        const int di = tap / 3, dj = tap % 3;
        __syncthreads();   // prev tap's reads (and W build) done
        for (int idx = tid; idx < 64 * 16; idx += 256) {
            int m = idx >> 4, c4 = idx & 15;
            int g = g0 + m;
            int bb_ = g / (OH * 2);
            int rem = g - bb_ * (OH * 2);
            int p = rem >> 1;
            int qq = 256 + (rem & 1);
            int r = p - di, cc = qq - dj;
            float4 v = make_float4(0.f, 0.f, 0.f, 0.f);
            if (g < NTPX && r >= 0 && r < IH && cc < IW)
                v = __ldg((const float4*)(gin +
                    ((((size_t)bb_ * IH + r) * IW + cc) * NCH) + c4 * 4));
            __half2 h01 = make_half2(__float2half_rn(v.x), __float2half_rn(v.y));
            __half2 h23 = make_half2(__float2half_rn(v.z), __float2half_rn(v.w));
            uint32_t off = (uint32_t)m * 128 + (uint32_t)c4 * 8;
            uint32_t sw = off ^ ((off >> 3) & 0x70);
            *(uint2*)(smem + SM_A + sw) = make_uint2(*(uint32_t*)&h01, *(uint32_t*)&h23);
        }
        __syncthreads();

        const uint32_t bb = sb + SM_B + (uint32_t)tap * B_TAP;
#pragma unroll
        for (int s = 0; s < 4; s++) {
            const uint32_t kx = (uint32_t)s * 32 + kcl;
            uint32_t B0[4], B1[4], A[4];
            ldm4(B0, bb + tbrow0 + (kx ^ tbm0));
            ldm4(B1, bb + tbrow1 + (kx ^ tbm1));
            ldm4(A, sb + SM_A + arow + (kx ^ am));
            mma16816(ct[0], A, B0[0], B0[2]);
            mma16816(ct[1], A, B0[1], B0[3]);
            mma16816(ct[2], A, B1[0], B1[2]);
            mma16816(ct[3], A, B1[1], B1[3]);
        }
    }

    const int m0 = tm * 16 + (lane >> 2);
#pragma unroll
    for (int half = 0; half < 2; half++) {
        const int g = g0 + m0 + half * 8;
        if (g < NTPX) {
            const int bb_ = g / (OH * 2);
            const int rem = g - bb_ * (OH * 2);
            const int p = rem >> 1;
            const int qq = 256 + (rem & 1);
            float* orow = gout + (((size_t)bb_ * OH + p) * OW + qq) * NCH;
#pragma unroll
            for (int nt = 0; nt < 4; nt++) {
                const int co = tn * 32 + nt * 8 + (lane & 3) * 2;
                *(float2*)(orow + co) =
                    make_float2(ct[nt][half * 2], ct[nt][half * 2 + 1]);
            }
        }
    }
}

// ---- kernel 2: main MMA kernel ----
__global__ void __launch_bounds__(NTHR, 1)
tconv_mma_kernel(const float* __restrict__ gw, float* __restrict__ gout)
{
    extern __shared__ char smem[];
    const uint32_t sb = smem_u32(smem);
    const int tid = threadIdx.x;
    const int lane = tid & 31;
    const int wid = tid >> 5;
    const int warp_m = wid & 3;          // 16-px group
    const int warp_n = (wid >> 2) & 1;   // 32-co group
    const int warp_g = wid >> 3;         // row-pair 0..2

    // ---- weight convert: gw[ci][co][tap] -> smem W^T[co][ci] fp16 ----
    for (int e = tid; e < NCH * NCH; e += NTHR) {
        int ci = e >> 6, co = e & 63;
        const float* wp = gw + (size_t)e * 9;
        uint32_t off = (uint32_t)co * 128 + (uint32_t)ci * 2;
        uint32_t sw = off ^ ((off >> 3) & 0x70);
#pragma unroll
        for (int tap = 0; tap < 9; tap++) {
            __half h = __float2half_rn(wp[tap]);
            *(unsigned short*)(smem + SM_B + tap * B_TAP + sw) = __half_as_ushort(h);
        }
    }

    // ldmatrix lane maps
    const int lm = (lane & 7) + ((lane >> 3) & 1) * 8;
    const uint32_t kcl = (uint32_t)((lane >> 4) & 1) * 16;
    const int nl0 = warp_n * 32 + lm;
    const int nl1 = nl0 + 16;
    const uint32_t brow0 = (uint32_t)nl0 * 128, bm0 = (uint32_t)(nl0 & 7) << 4;
    const uint32_t brow1 = (uint32_t)nl1 * 128, bm1 = (uint32_t)(nl1 & 7) << 4;

    const int u0 = (int)(((long long)blockIdx.x * NMAIN) / NCTA);
    const int u1 = (int)(((long long)(blockIdx.x + 1) * NMAIN) / NCTA);
    int cur_strip = -1;

    for (int u = u0; u < u1; u++) {
        const int strip = u / NPB;
        const int pb = u - strip * NPB;
        const int p0 = pb * 6;
        const int b = strip >> 2;
        const int qg0 = (strip & 3) * 64;

        bool pf = false;
        if (strip != cur_strip) {
            cpwait<0>();
            __syncthreads();   // prior reads done before slot overwrite
            int rlo = p0 - 2 < 0 ? 0 : p0 - 2;
            int rhi = p0 + 5 > IH - 1 ? IH - 1 : p0 + 5;
            for (int r = rlo; r <= rhi; r++) {
                const uint32_t dslot = sb + SM_A + (uint32_t)(r & 15) * A_SLOT;
                const unsigned char* srow = g_fp16 + ((size_t)b * IH + r) * GROW;
                for (int idx = tid; idx < 544; idx += NTHR) {
                    int j = idx >> 3, ch = idx & 7;
                    int pa = qg0 - 2 + j;
                    uint32_t d = dslot + (uint32_t)j * 128 + (uint32_t)ch * 16;
                    if (pa >= 0 && pa < IW)
                        cp16(d, srow + (size_t)pa * 128 + ch * 16);
                    else
                        *(uint4*)(smem + (d - sb)) = make_uint4(0, 0, 0, 0);
                }
            }
            cpcommit();
            cur_strip = strip;
        }
        // prefetch next unit's rows (same strip only)
        if (u + 1 < u1 && (u + 1) / NPB == strip) {
            int rlo = p0 + 6;
            int rhi = p0 + 11 > IH - 1 ? IH - 1 : p0 + 11;
            for (int r = rlo; r <= rhi; r++) {
                const uint32_t dslot = sb + SM_A + (uint32_t)(r & 15) * A_SLOT;
                const unsigned char* srow = g_fp16 + ((size_t)b * IH + r) * GROW;
                for (int idx = tid; idx < 544; idx += NTHR) {
                    int j = idx >> 3, ch = idx & 7;
                    int pa = qg0 - 2 + j;
                    uint32_t d = dslot + (uint32_t)j * 128 + (uint32_t)ch * 16;
                    if (pa >= 0 && pa < IW)
                        cp16(d, srow + (size_t)pa * 128 + ch * 16);
                    else
                        *(uint4*)(smem + (d - sb)) = make_uint4(0, 0, 0, 0);
                }
            }
            cpcommit();
            pf = true;
        }
        if (pf) cpwait<1>(); else cpwait<0>();
        __syncthreads();   // this unit's rows visible to all warps

        // ---- compute: this warp's rows {pw, pw+1}, 16px x 32co each ----
        // A rolling window: input row rp = pw-2+t feeds rr=0 at di=2-t and
        // rr=1 at di=3-t, so each A fragment is live across 2 di steps.
        const int pw = p0 + warp_g * 2;
        float c[2][4][4];
#pragma unroll
        for (int rr = 0; rr < 2; rr++)
#pragma unroll
            for (int i = 0; i < 4; i++)
#pragma unroll
                for (int j = 0; j < 4; j++) c[rr][i][j] = 0.f;

        uint32_t aB[4];
        bool okA[4];
#pragma unroll
        for (int t = 0; t < 4; t++) {
            int rp = pw - 2 + t;
            okA[t] = (rp >= 0 && rp < IH);
            aB[t] = sb + SM_A + (uint32_t)(rp & 15) * A_SLOT;
        }

#pragma unroll
        for (int dj = 0; dj < 3; dj++) {
            const int rowi = warp_m * 16 + lm + 2 - dj;
            const uint32_t arow = (uint32_t)rowi * 128;
            // data swizzled by absolute px pa = qg0-2+rowi; qg0%8==0 -> +6
            const uint32_t am = (uint32_t)((rowi + 6) & 7) << 4;
#pragma unroll
            for (int s = 0; s < 4; s++) {
                const uint32_t kx = (uint32_t)s * 32 + kcl;
                const uint32_t ax = arow + (kx ^ am);
                uint32_t Ahi[4], Alo[4];
                if (okA[3]) ldm4(Ahi, aB[3] + ax);   // rp = pw+1
#pragma unroll
                for (int di = 0; di < 3; di++) {
                    const int tlo = 2 - di;
                    if (okA[tlo]) ldm4(Alo, aB[tlo] + ax);   // rp = pw-di
                    const uint32_t bb = sb + SM_B + (uint32_t)(di * 3 + dj) * B_TAP;
                    uint32_t B0[4], B1[4];
                    ldm4(B0, bb + brow0 + (kx ^ bm0));
                    ldm4(B1, bb + brow1 + (kx ^ bm1));
                    if (okA[tlo]) {            // rr=0, row pw, A = Alo
                        mma16816(c[0][0], Alo, B0[0], B0[2]);
                        mma16816(c[0][1], Alo, B0[1], B0[3]);
                        mma16816(c[0][2], Alo, B1[0], B1[2]);
                        mma16816(c[0][3], Alo, B1[1], B1[3]);
                    }
                    if (okA[tlo + 1]) {        // rr=1, row pw+1, A = Ahi
                        mma16816(c[1][0], Ahi, B0[0], B0[2]);
                        mma16816(c[1][1], Ahi, B0[1], B0[3]);
                        mma16816(c[1][2], Ahi, B1[0], B1[2]);
                        mma16816(c[1][3], Ahi, B1[1], B1[3]);
                    }
#pragma unroll
                    for (int k = 0; k < 4; k++) Ahi[k] = Alo[k];
                }
            }
        }

        // ---- store both rows ----
        const int q = qg0 + warp_m * 16 + (lane >> 2);
#pragma unroll
        for (int rr = 0; rr < 2; rr++) {
            const int p = pw + rr;
            float* orow = gout + (((size_t)b * OH + p) * OW + q) * NCH;
#pragma unroll
            for (int nt = 0; nt < 4; nt++) {
                const int co = warp_n * 32 + nt * 8 + (lane & 3) * 2;
                *(float2*)(orow + co) = make_float2(c[rr][nt][0], c[rr][nt][1]);
                *(float2*)(orow + 8 * NCH + co) = make_float2(c[rr][nt][2], c[rr][nt][3]);
            }
        }
        __syncthreads();   // all reads done before next iter's cp.async writes
    }
}

extern "C" void kernel_launch(void* const* d_in, const int* in_sizes, int n_in,
                              void* d_out, int out_size)
{
    const float* gin = (const float*)d_in[0]; // [8,256,256,64]
    const float* gw  = (const float*)d_in[1]; // [64,64,3,3]
    float* gout = (float*)d_out;              // [8,258,258,64]

    cudaFuncSetAttribute(pre_and_tail_kernel,
                         cudaFuncAttributeMaxDynamicSharedMemorySize, SM_PT);
    cudaFuncSetAttribute(tconv_mma_kernel,
                         cudaFuncAttributeMaxDynamicSharedMemorySize, SM_TOTAL);
    pre_and_tail_kernel<<<PREBLKS + NTAIL, 256, SM_PT>>>(gin, gw, gout);
    tconv_mma_kernel<<<NCTA, NTHR, SM_TOTAL>>>(gw, gout);
}

// round 13
// speedup vs baseline: 1.1133x; 1.1133x over previous
#include <cuda_runtime.h>
#include <cuda_fp16.h>
#include <cstdint>

// Transposed conv (full conv): B=8, H=W=256, CIN=COUT=64, 3x3, fp32 NHWC.
// out[b,p,q,co] = sum_{di,dj,ci} in[b,p-di,q-dj,ci] * ker[ci,co,di,dj]
// Kernel 1: preconvert fp32->fp16 (pre-swizzled A layout, __device__ global).
// Kernel 2: mma.sync fp16 implicit GEMM; rows via cp.async (pure byte copy);
// warp tile 16px x 32co x 3 rows with a 5-row A window + B amortized over
// 3 rows (0.306 ldm4/mma). Tail columns (q=256,257) inside kernel 2.

#define IH 256
#define IW 256
#define NCH 64
#define OH 258
#define OW 258

// main-kernel smem layout
#define B_TAP 8192                        // per tap: 64 co rows x 128B fp16
#define SM_B 0
#define SM_A (9 * B_TAP)                  // 73728
#define A_SLOT 8704                       // 68 px segs * 128B
#define NSLOT 16
#define SM_TOTAL (SM_A + NSLOT * A_SLOT)  // 212992

#define NPB 43                            // 6-row units per strip (43*6=258)
#define NSTRIP 32                         // 8 b * 4 q-strips of 64
#define NMAIN (NSTRIP * NPB)              // 1376
#define NTPX (8 * OH * 2)                 // 4128 tail pixels
#define NTAIL 65
#define NCTA 152
#define NTHR 512

#define GROW 32768                        // bytes per pre-converted input row

// 64MB pre-converted fp16 input: [b][r][pa][ci], 128B per px, SW128 by abs px
__device__ __align__(128) unsigned char g_fp16[(size_t)8 * IH * GROW];

__device__ __forceinline__ uint32_t smem_u32(const void* p) {
    uint32_t a;
    asm("{ .reg .u64 t; cvta.to.shared.u64 t, %1; cvt.u32.u64 %0, t; }" : "=r"(a) : "l"(p));
    return a;
}
__device__ __forceinline__ void ldm4(uint32_t* r, uint32_t a) {
    asm volatile("ldmatrix.sync.aligned.m8n8.x4.shared.b16 {%0,%1,%2,%3}, [%4];"
                 : "=r"(r[0]), "=r"(r[1]), "=r"(r[2]), "=r"(r[3]) : "r"(a));
}
__device__ __forceinline__ void mma16816(float* c, const uint32_t* a,
                                         uint32_t b0, uint32_t b1) {
    asm volatile(
        "mma.sync.aligned.m16n8k16.row.col.f32.f16.f16.f32 "
        "{%0,%1,%2,%3}, {%4,%5,%6,%7}, {%8,%9}, {%0,%1,%2,%3};"
        : "+f"(c[0]), "+f"(c[1]), "+f"(c[2]), "+f"(c[3])
        : "r"(a[0]), "r"(a[1]), "r"(a[2]), "r"(a[3]), "r"(b0), "r"(b1));
}
__device__ __forceinline__ void cp16(uint32_t dst, const void* src) {
    asm volatile(
        "{ .reg .u64 g; cvta.to.global.u64 g, %1; cp.async.cg.shared.global [%0], [g], 16; }"
        :: "r"(dst), "l"(src) : "memory");
}
__device__ __forceinline__ void cpcommit() {
    asm volatile("cp.async.commit_group;" ::: "memory");
}
template <int N>
__device__ __forceinline__ void cpwait() {
    asm volatile("cp.async.wait_group %0;" :: "n"(N) : "memory");
}

// ---- kernel 1: preconvert one input row to fp16, swizzled by absolute px ----
__global__ void __launch_bounds__(256)
preconvert_kernel(const float* __restrict__ gin)
{
    const int r = blockIdx.x;
    const int b = blockIdx.y;
    const float* src = gin + ((size_t)b * IH + r) * IW * NCH;
    unsigned char* dst = g_fp16 + ((size_t)b * IH + r) * GROW;
#pragma unroll 4
    for (int idx = threadIdx.x; idx < IW * 16; idx += 256) {
        int pa = idx >> 4, c4 = idx & 15;
        float4 v = __ldg((const float4*)(src + (size_t)pa * NCH + c4 * 4));
        __half2 h01 = make_half2(__float2half_rn(v.x), __float2half_rn(v.y));
        __half2 h23 = make_half2(__float2half_rn(v.z), __float2half_rn(v.w));
        uint32_t off = (uint32_t)pa * 128 + (uint32_t)c4 * 8;
        uint32_t sw = off ^ ((off >> 3) & 0x70);
        *(uint2*)(dst + sw) = make_uint2(*(uint32_t*)&h01, *(uint32_t*)&h23);
    }
}

// ---- kernel 2: main MMA kernel (+ tail units on blocks 0..64) ----
__global__ void __launch_bounds__(NTHR, 1)
tconv_mma_kernel(const float* __restrict__ gin, const float* __restrict__ gw,
                 float* __restrict__ gout)
{
    extern __shared__ char smem[];
    const uint32_t sb = smem_u32(smem);
    const int tid = threadIdx.x;
    const int lane = tid & 31;
    const int wid = tid >> 5;
    const int warp_m = wid & 3;          // 16-px group
    const int warp_n = (wid >> 2) & 1;   // 32-co group
    const int warp_g = (wid >> 3) & 1;   // row-triple 0..1

    // ---- weight convert: gw[ci][co][tap] -> smem W^T[co][ci] fp16 ----
    for (int e = tid; e < NCH * NCH; e += NTHR) {
        int ci = e >> 6, co = e & 63;
        const float* wp = gw + (size_t)e * 9;
        uint32_t off = (uint32_t)co * 128 + (uint32_t)ci * 2;
        uint32_t sw = off ^ ((off >> 3) & 0x70);
#pragma unroll
        for (int tap = 0; tap < 9; tap++) {
            __half h = __float2half_rn(wp[tap]);
            *(unsigned short*)(smem + SM_B + tap * B_TAP + sw) = __half_as_ushort(h);
        }
    }

    // ldmatrix lane maps
    const int lm = (lane & 7) + ((lane >> 3) & 1) * 8;
    const uint32_t kcl = (uint32_t)((lane >> 4) & 1) * 16;
    const int nl0 = warp_n * 32 + lm;
    const int nl1 = nl0 + 16;
    const uint32_t brow0 = (uint32_t)nl0 * 128, bm0 = (uint32_t)(nl0 & 7) << 4;
    const uint32_t brow1 = (uint32_t)nl1 * 128, bm1 = (uint32_t)(nl1 & 7) << 4;

    const int u0 = (int)(((long long)blockIdx.x * NMAIN) / NCTA);
    const int u1 = (int)(((long long)(blockIdx.x + 1) * NMAIN) / NCTA);
    int cur_strip = -1;

    for (int u = u0; u < u1; u++) {
        const int strip = u / NPB;
        const int pb = u - strip * NPB;
        const int p0 = pb * 6;
        const int b = strip >> 2;
        const int qg0 = (strip & 3) * 64;

        bool pf = false;
        if (strip != cur_strip) {
            cpwait<0>();
            __syncthreads();   // prior reads done before slot overwrite
            int rlo = p0 - 2 < 0 ? 0 : p0 - 2;
            int rhi = p0 + 5 > IH - 1 ? IH - 1 : p0 + 5;
            for (int r = rlo; r <= rhi; r++) {
                const uint32_t dslot = sb + SM_A + (uint32_t)(r & 15) * A_SLOT;
                const unsigned char* srow = g_fp16 + ((size_t)b * IH + r) * GROW;
                for (int idx = tid; idx < 544; idx += NTHR) {
                    int j = idx >> 3, ch = idx & 7;
                    int pa = qg0 - 2 + j;
                    uint32_t d = dslot + (uint32_t)j * 128 + (uint32_t)ch * 16;
                    if (pa >= 0 && pa < IW)
                        cp16(d, srow + (size_t)pa * 128 + ch * 16);
                    else
                        *(uint4*)(smem + (d - sb)) = make_uint4(0, 0, 0, 0);
                }
            }
            cpcommit();
            cur_strip = strip;
        }
        // prefetch next unit's rows (same strip only)
        if (u + 1 < u1 && (u + 1) / NPB == strip) {
            int rlo = p0 + 6;
            int rhi = p0 + 11 > IH - 1 ? IH - 1 : p0 + 11;
            for (int r = rlo; r <= rhi; r++) {
                const uint32_t dslot = sb + SM_A + (uint32_t)(r & 15) * A_SLOT;
                const unsigned char* srow = g_fp16 + ((size_t)b * IH + r) * GROW;
                for (int idx = tid; idx < 544; idx += NTHR) {
                    int j = idx >> 3, ch = idx & 7;
                    int pa = qg0 - 2 + j;
                    uint32_t d = dslot + (uint32_t)j * 128 + (uint32_t)ch * 16;
                    if (pa >= 0 && pa < IW)
                        cp16(d, srow + (size_t)pa * 128 + ch * 16);
                    else
                        *(uint4*)(smem + (d - sb)) = make_uint4(0, 0, 0, 0);
                }
            }
            cpcommit();
            pf = true;
        }
        if (pf) cpwait<1>(); else cpwait<0>();
        __syncthreads();   // this unit's rows visible to all warps

        // ---- compute: this warp's rows {pw..pw+2}, 16px x 32co each ----
        // 5-row A window: input row rp = pw-2+t feeds out row rr at di = rr+2-t.
        const int pw = p0 + warp_g * 3;
        float c[3][4][4];
#pragma unroll
        for (int rr = 0; rr < 3; rr++)
#pragma unroll
            for (int i = 0; i < 4; i++)
#pragma unroll
                for (int j = 0; j < 4; j++) c[rr][i][j] = 0.f;

        uint32_t aB[5];
        bool okA[5];
#pragma unroll
        for (int t = 0; t < 5; t++) {
            int rp = pw - 2 + t;
            okA[t] = (rp >= 0 && rp < IH);
            aB[t] = sb + SM_A + (uint32_t)(rp & 15) * A_SLOT;
        }

#pragma unroll
        for (int dj = 0; dj < 3; dj++) {
            const int rowi = warp_m * 16 + lm + 2 - dj;
            const uint32_t arow = (uint32_t)rowi * 128;
            // data swizzled by absolute px pa = qg0-2+rowi; qg0%8==0 -> +6
            const uint32_t am = (uint32_t)((rowi + 6) & 7) << 4;
#pragma unroll
            for (int s = 0; s < 4; s++) {
                const uint32_t kx = (uint32_t)s * 32 + kcl;
                const uint32_t ax = arow + (kx ^ am);
                uint32_t Af[5][4];
#pragma unroll
                for (int t = 0; t < 5; t++)
                    if (okA[t]) ldm4(Af[t], aB[t] + ax);
#pragma unroll
                for (int di = 0; di < 3; di++) {
                    const uint32_t bb = sb + SM_B + (uint32_t)(di * 3 + dj) * B_TAP;
                    uint32_t B0[4], B1[4];
                    ldm4(B0, bb + brow0 + (kx ^ bm0));
                    ldm4(B1, bb + brow1 + (kx ^ bm1));
#pragma unroll
                    for (int rr = 0; rr < 3; rr++) {
                        const int t = rr + 2 - di;
                        if (okA[t]) {
                            mma16816(c[rr][0], Af[t], B0[0], B0[2]);
                            mma16816(c[rr][1], Af[t], B0[1], B0[3]);
                            mma16816(c[rr][2], Af[t], B1[0], B1[2]);
                            mma16816(c[rr][3], Af[t], B1[1], B1[3]);
                        }
                    }
                }
            }
        }

        // ---- store all three rows ----
        const int q = qg0 + warp_m * 16 + (lane >> 2);
#pragma unroll
        for (int rr = 0; rr < 3; rr++) {
            const int p = pw + rr;
            float* orow = gout + (((size_t)b * OH + p) * OW + q) * NCH;
#pragma unroll
            for (int nt = 0; nt < 4; nt++) {
                const int co = warp_n * 32 + nt * 8 + (lane & 3) * 2;
                *(float2*)(orow + co) = make_float2(c[rr][nt][0], c[rr][nt][1]);
                *(float2*)(orow + 8 * NCH + co) = make_float2(c[rr][nt][2], c[rr][nt][3]);
            }
        }
        __syncthreads();   // all reads done before next iter's cp.async writes
    }

    // ================= tail units: q in {256,257}, 64 px per unit ============
    if (blockIdx.x < NTAIL) {
        const int g0 = blockIdx.x * 64;
        const int tm = wid & 3;
        const int tn = (wid >> 2) & 1;
        const bool tact = (wid < 8);

        const int tnl0 = tn * 32 + lm;
        const int tnl1 = tnl0 + 16;
        const uint32_t tbrow0 = (uint32_t)tnl0 * 128, tbm0 = (uint32_t)(tnl0 & 7) << 4;
        const uint32_t tbrow1 = (uint32_t)tnl1 * 128, tbm1 = (uint32_t)(tnl1 & 7) << 4;
        const int rowi = tm * 16 + lm;
        const uint32_t arow = (uint32_t)rowi * 128;
        const uint32_t am = (uint32_t)(rowi & 7) << 4;

        float ct[4][4];
#pragma unroll
        for (int i = 0; i < 4; i++)
#pragma unroll
            for (int j = 0; j < 4; j++) ct[i][j] = 0.f;

        for (int tap = 0; tap < 9; tap++) {
            const int di = tap / 3, dj = tap % 3;
            __syncthreads();   // prev tap's reads done / main loop done
            for (int idx = tid; idx < 64 * 16; idx += NTHR) {
                int m = idx >> 4, c4 = idx & 15;
                int g = g0 + m;
                int bb_ = g / (OH * 2);
                int rem = g - bb_ * (OH * 2);
                int p = rem >> 1;
                int qq = 256 + (rem & 1);
                int r = p - di, cc = qq - dj;
                float4 v = make_float4(0.f, 0.f, 0.f, 0.f);
                if (g < NTPX && r >= 0 && r < IH && cc < IW)
                    v = __ldg((const float4*)(gin +
                        ((((size_t)bb_ * IH + r) * IW + cc) * NCH) + c4 * 4));
                __half2 h01 = make_half2(__float2half_rn(v.x), __float2half_rn(v.y));
                __half2 h23 = make_half2(__float2half_rn(v.z), __float2half_rn(v.w));
                uint32_t off = (uint32_t)m * 128 + (uint32_t)c4 * 8;
                uint32_t sw = off ^ ((off >> 3) & 0x70);
                *(uint2*)(smem + SM_A + sw) = make_uint2(*(uint32_t*)&h01, *(uint32_t*)&h23);
            }
            __syncthreads();

            if (tact) {
                const uint32_t bb = sb + SM_B + (uint32_t)tap * B_TAP;
#pragma unroll
                for (int s = 0; s < 4; s++) {
                    const uint32_t kx = (uint32_t)s * 32 + kcl;
                    uint32_t B0[4], B1[4], A[4];
                    ldm4(B0, bb + tbrow0 + (kx ^ tbm0));
                    ldm4(B1, bb + tbrow1 + (kx ^ tbm1));
                    ldm4(A, sb + SM_A + arow + (kx ^ am));
                    mma16816(ct[0], A, B0[0], B0[2]);
                    mma16816(ct[1], A, B0[1], B0[3]);
                    mma16816(ct[2], A, B1[0], B1[2]);
                    mma16816(ct[3], A, B1[1], B1[3]);
                }
            }
        }

        if (tact) {
            const int m0 = tm * 16 + (lane >> 2);
#pragma unroll
            for (int half = 0; half < 2; half++) {
                const int g = g0 + m0 + half * 8;
                if (g < NTPX) {
                    const int bb_ = g / (OH * 2);
                    const int rem = g - bb_ * (OH * 2);
                    const int p = rem >> 1;
                    const int qq = 256 + (rem & 1);
                    float* orow = gout + (((size_t)bb_ * OH + p) * OW + qq) * NCH;
#pragma unroll
                    for (int nt = 0; nt < 4; nt++) {
                        const int co = tn * 32 + nt * 8 + (lane & 3) * 2;
                        *(float2*)(orow + co) =
                            make_float2(ct[nt][half * 2], ct[nt][half * 2 + 1]);
                    }
                }
            }
        }
    }
}

extern "C" void kernel_launch(void* const* d_in, const int* in_sizes, int n_in,
                              void* d_out, int out_size)
{
    const float* gin = (const float*)d_in[0]; // [8,256,256,64]
    const float* gw  = (const float*)d_in[1]; // [64,64,3,3]
    float* gout = (float*)d_out;              // [8,258,258,64]

    cudaFuncSetAttribute(tconv_mma_kernel,
                         cudaFuncAttributeMaxDynamicSharedMemorySize, SM_TOTAL);
    preconvert_kernel<<<dim3(IH, 8), 256>>>(gin);
    tconv_mma_kernel<<<NCTA, NTHR, SM_TOTAL>>>(gin, gw, gout);
}